// round 8
// baseline (speedup 1.0000x reference)
#include <cuda_runtime.h>
#include <cuda_bf16.h>
#include <math.h>

#define BN     8192
#define ZD     128
#define NC     62
#define NP     93
#define P2     96        // padded proxies
#define NA     2730      // anchors 0,3,...,8187
#define EPSV   1e-6f
#define EPS2T  1.28e-10f // ZD*EPS^2
#define SZP    132       // padded smem z row (floats)
#define SDP    100       // padded smem dist row (floats), 4-aligned
#define DTHR   768
#define HB_W   8
#define HGRID  ((NA + HB_W - 1) / HB_W)   // 342

// ---------------- persistent scratch (device globals, zero-init) -------------
__device__ float g_prxT[ZD * P2];      // [k][p], pads stay 0
__device__ float g_pss[P2];
__device__ float g_psum[P2];
__device__ int   g_clsidx[BN];
__device__ int2  g_ab[NA];             // per-anchor class-list [lo,hi)
__device__ int   g_pidx[NA];           // nearest proxy per anchor
__device__ float g_Dpz[P2 * BN];       // dist(proxy p, z j), eps sign psum-zs
__device__ float g_DT [BN * P2];       // dist(z j, proxy p), eps sign zs-psum
__device__ float g_loss[NA];
__device__ unsigned int g_done;
__device__ unsigned int g_flag;        // prxT-ready; reset by k_hard last block

// ---------------- helpers ---------------------------------------------------
__device__ __forceinline__ float warp_sum(float v) {
#pragma unroll
    for (int o = 16; o; o >>= 1) v += __shfl_xor_sync(0xffffffffu, v, o);
    return v;
}
__device__ __forceinline__ void warp_argmin(float& v, int& i) {
#pragma unroll
    for (int o = 16; o; o >>= 1) {
        float v2 = __shfl_xor_sync(0xffffffffu, v, o);
        int   i2 = __shfl_xor_sync(0xffffffffu, i, o);
        if (v2 < v || (v2 == v && i2 < i)) { v = v2; i = i2; }
    }
}
__device__ __forceinline__ void warp_argmax(float& v, int& i) {
#pragma unroll
    for (int o = 16; o; o >>= 1) {
        float v2 = __shfl_xor_sync(0xffffffffu, v, o);
        int   i2 = __shfl_xor_sync(0xffffffffu, i, o);
        if (v2 > v || (v2 == v && i2 < i)) { v = v2; i = i2; }
    }
}

// ============ K1: distances + nearest-proxy + class lists ====================
// grid: 130 x 768. Block 0: proxies -> global prxT, set flag.
// Block 1: class scatter + per-anchor bounds. Blocks 2..129: 96x64 tiles.
__global__ void __launch_bounds__(DTHR) k_dist(const float* __restrict__ z,
                                               const int* __restrict__ y_idx,
                                               const int* __restrict__ y_map,
                                               const float* __restrict__ proxies) {
    __shared__ float s_z[64 * SZP];          // 33.8 KB (also reused as dist tile)
    __shared__ float s_zz[64], s_zs[64];

    int b = blockIdx.x, t = threadIdx.x;
    int w = t >> 5, lane = t & 31;

    if (b == 0) {      // ---- producer: normalize proxies into GLOBAL prxT ----
        for (int p = w; p < NP; p += 24) {
            float4 v = ((const float4*)(proxies + p * ZD))[lane];
            float ss = warp_sum(v.x * v.x + v.y * v.y + v.z * v.z + v.w * v.w);
            float inv = 1.f / fmaxf(sqrtf(ss), 1e-12f);
            float4 o = make_float4(v.x * inv, v.y * inv, v.z * inv, v.w * inv);
            int k0 = 4 * lane;
            g_prxT[(k0 + 0) * P2 + p] = o.x;
            g_prxT[(k0 + 1) * P2 + p] = o.y;
            g_prxT[(k0 + 2) * P2 + p] = o.z;
            g_prxT[(k0 + 3) * P2 + p] = o.w;
            float so  = warp_sum(o.x + o.y + o.z + o.w);
            float so2 = warp_sum(o.x * o.x + o.y * o.y + o.z * o.z + o.w * o.w);
            if (lane == 0) { g_psum[p] = so; g_pss[p] = so2; }
        }
        // zero pad columns (defensive; zero-init covers first run)
        for (int idx = t; idx < ZD * 3; idx += DTHR)
            g_prxT[(idx / 3) * P2 + NP + (idx % 3)] = 0.f;
        if (t >= NP && t < P2) { g_pss[t] = 0.f; g_psum[t] = 0.f; }
        __syncthreads();
        if (t == 0) { __threadfence(); *(volatile unsigned int*)&g_flag = 1u; }
        return;
    }

    if (b == 1) {      // ---- service: scatter + per-anchor bounds ----
        __shared__ int s_inv[NC];
        __shared__ int cnt[NC], cur[NC], start[NC + 1];
        if (t < NC) { s_inv[y_map[t]] = t; cnt[t] = 0; }
        __syncthreads();
        for (int j = t; j < BN; j += DTHR) atomicAdd(&cnt[s_inv[y_idx[j]]], 1);
        __syncthreads();
        if (t == 0) {
            int acc = 0;
            for (int c = 0; c < NC; c++) { start[c] = acc; acc += cnt[c]; }
            start[NC] = acc;
        }
        __syncthreads();
        if (t < NC) cur[t] = start[t];
        __syncthreads();
        for (int j = t; j < BN; j += DTHR) {
            int c = s_inv[y_idx[j]];
            int pos = atomicAdd(&cur[c], 1);
            g_clsidx[pos] = j;
        }
        for (int i = t; i < NA; i += DTHR) {
            int c = s_inv[y_idx[3 * i]];
            g_ab[i] = make_int2(start[c], start[c + 1]);
        }
        return;
    }

    // ---------------- tile block: rows [B0, B0+64) ----------------
    int B0 = (b - 2) * 64;
    const float4* z4 = (const float4*)z;
    for (int idx = t; idx < 64 * 32; idx += DTHR) {
        int r = idx >> 5, q = idx & 31;          // r warp-uniform
        float4 v = z4[(size_t)(B0 + r) * 32 + q];
        float* dst = &s_z[r * SZP + 4 * q];
        dst[0] = v.x; dst[1] = v.y; dst[2] = v.z; dst[3] = v.w;
        float s  = (v.x + v.y) + (v.z + v.w);
        float ss = (v.x * v.x + v.y * v.y) + (v.z * v.z + v.w * v.w);
#pragma unroll
        for (int o = 16; o; o >>= 1) {
            s  += __shfl_xor_sync(0xffffffffu, s, o);
            ss += __shfl_xor_sync(0xffffffffu, ss, o);
        }
        if (lane == 0) { s_zs[r] = s; s_zz[r] = ss; }
    }
    // wait for prxT (usually already set — staging above hides it)
    if (t == 0) { while (*(volatile unsigned int*)&g_flag == 0u) { } }
    __syncthreads();
    __threadfence();   // acquire

    // ---- mainloop: thread tile 4 proxies x 2 samples (24 x 32 groups) ----
    int pg = t % 24, sg = t / 24;
    int p0 = 4 * pg, s0 = 2 * sg;
    const float4* prxT4 = (const float4*)g_prxT;

    float acc[4][2];
#pragma unroll
    for (int j = 0; j < 4; j++) { acc[j][0] = 0.f; acc[j][1] = 0.f; }

#pragma unroll 4
    for (int k = 0; k < ZD; k++) {
        float4 pv = __ldg(&prxT4[k * 24 + pg]);   // 48 KB, L1-resident
        float zv0 = s_z[(s0 + 0) * SZP + k];
        float zv1 = s_z[(s0 + 1) * SZP + k];
        acc[0][0] = fmaf(pv.x, zv0, acc[0][0]); acc[0][1] = fmaf(pv.x, zv1, acc[0][1]);
        acc[1][0] = fmaf(pv.y, zv0, acc[1][0]); acc[1][1] = fmaf(pv.y, zv1, acc[1][1]);
        acc[2][0] = fmaf(pv.z, zv0, acc[2][0]); acc[2][1] = fmaf(pv.z, zv1, acc[2][1]);
        acc[3][0] = fmaf(pv.w, zv0, acc[3][0]); acc[3][1] = fmaf(pv.w, zv1, acc[3][1]);
    }

    int sBase = B0 + s0;
    float pssv[4], psmv[4], zzv[2], zsv[2];
#pragma unroll
    for (int j = 0; j < 4; j++) { pssv[j] = g_pss[p0 + j]; psmv[j] = g_psum[p0 + j]; }
#pragma unroll
    for (int i = 0; i < 2; i++) { zzv[i] = s_zz[s0 + i]; zsv[i] = s_zs[s0 + i]; }

    float dpz[4][2], dzp[4][2];
#pragma unroll
    for (int j = 0; j < 4; j++)
#pragma unroll
        for (int i = 0; i < 2; i++) {
            float base = zzv[i] + pssv[j] - 2.f * acc[j][i];
            float e = 2.f * EPSV * (psmv[j] - zsv[i]);
            dpz[j][i] = sqrtf(fmaxf(base + e + EPS2T, 0.f));
            dzp[j][i] = sqrtf(fmaxf(base - e + EPS2T, 0.f));
        }

#pragma unroll
    for (int j = 0; j < 4; j++)
        *(float2*)(g_Dpz + (size_t)(p0 + j) * BN + sBase) =
            make_float2(dpz[j][0], dpz[j][1]);
#pragma unroll
    for (int i = 0; i < 2; i++)
        *(float4*)(g_DT + (size_t)(sBase + i) * P2 + p0) =
            make_float4(dzp[0][i], dzp[1][i], dzp[2][i], dzp[3][i]);

    // ---- nearest-proxy argmin for anchor rows in this tile ----
    __syncthreads();                       // mainloop done; safe to reuse s_z
    float* s_d = s_z;                      // [64][SDP]
#pragma unroll
    for (int i = 0; i < 2; i++)
        *(float4*)(s_d + (s0 + i) * SDP + p0) =
            make_float4(dzp[0][i], dzp[1][i], dzp[2][i], dzp[3][i]);
    __syncthreads();

    int a0 = (B0 + 2) / 3;                 // first anchor with 3*a0 >= B0
    int aEnd = (B0 + 63) / 3;              // last anchor with 3*aEnd <= B0+63
    int anch = a0 + w;                     // warp per anchor row (<=22 <=24)
    if (anch <= aEnd && anch < NA) {
        int r = 3 * anch - B0;
        float bv = INFINITY; int bp = 0x7fffffff;
#pragma unroll
        for (int q = 0; q < 3; q++) {
            int p = lane + 32 * q;
            float d = (p < NP) ? s_d[r * SDP + p] : INFINITY;
            if (d < bv || (d == bv && p < bp)) { bv = d; bp = p; }
        }
        warp_argmin(bv, bp);
        if (lane == 0) g_pidx[anch] = bp;
    }
}

// ============ K2: warp-per-anchor: hardpos + lse + mean ======================
// grid: HGRID x 256
__global__ void __launch_bounds__(256) k_hard(float* __restrict__ out) {
    __shared__ float rbuf[8];
    __shared__ int s_last;
    int t = threadIdx.x, w = t >> 5, lane = t & 31;
    int i = blockIdx.x * HB_W + w;

    if (i < NA) {
        int a = 3 * i;
        int px = g_pidx[i];                  // broadcast load
        int2 ab = g_ab[i];
        const float* Drow = g_Dpz + (size_t)px * BN;
        float hb = -INFINITY; int hj = 0x7fffffff;
        for (int idx = ab.x + lane; idx < ab.y; idx += 64) {
            int j0 = g_clsidx[idx];
            int i2 = idx + 32;
            int j1 = (i2 < ab.y) ? g_clsidx[i2] : -1;
            if (j0 >= a) {
                float d = __ldg(Drow + j0);
                if (d > hb || (d == hb && j0 < hj)) { hb = d; hj = j0; }
            }
            if (j1 >= a) {
                float d = __ldg(Drow + j1);
                if (d > hb || (d == hb && j1 < hj)) { hb = d; hj = j1; }
            }
        }
        warp_argmax(hb, hj);                 // hj = j_p, hb = D_p

        const float* dtj = g_DT + (size_t)hj * P2;
        float nd0 = (lane      < NP) ? -__ldg(dtj + lane)      : -INFINITY;
        float nd1 = (lane + 32 < NP) ? -__ldg(dtj + lane + 32) : -INFINITY;
        float nd2 = (lane + 64 < NP) ? -__ldg(dtj + lane + 64) : -INFINITY;
        float m = fmaxf(nd0, fmaxf(nd1, nd2));
#pragma unroll
        for (int o = 16; o; o >>= 1) m = fmaxf(m, __shfl_xor_sync(0xffffffffu, m, o));
        float s = expf(nd0 - m) + expf(nd1 - m) + expf(nd2 - m);
        s = warp_sum(s);
        if (lane == 0) g_loss[i] = hb + (m + logf(s));
    }

    // ---- last block: deterministic mean + state reset ----
    __threadfence();
    __syncthreads();
    if (t == 0) s_last = (atomicAdd(&g_done, 1u) == (unsigned)(gridDim.x - 1));
    __syncthreads();
    if (s_last) {
        __threadfence();
        float s = 0.f;
        for (int k = t; k < NA; k += 256) s += g_loss[k];
        s = warp_sum(s);
        if (lane == 0) rbuf[w] = s;
        __syncthreads();
        if (t == 0) {
            float total = 0.f;
#pragma unroll
            for (int q = 0; q < 8; q++) total += rbuf[q];
            out[0] = total / (float)NA;
            g_done = 0;
            g_flag = 0;       // re-arm producer flag for next replay
        }
    }
}

// ---------------- launch ------------------------------------------------------
extern "C" void kernel_launch(void* const* d_in, const int* in_sizes, int n_in,
                              void* d_out, int out_size) {
    const float* z       = (const float*)d_in[0];
    const int*   y_idx   = (const int*)d_in[1];
    const float* proxies = (const float*)d_in[2];
    const int*   y_map   = (const int*)d_in[3];
    float*       out     = (float*)d_out;

    k_dist<<<130, DTHR>>>(z, y_idx, y_map, proxies);
    k_hard<<<HGRID, 256>>>(out);
}

// round 9
// speedup vs baseline: 1.3339x; 1.3339x over previous
#include <cuda_runtime.h>
#include <cuda_bf16.h>
#include <math.h>

#define BN     8192
#define ZD     128
#define NC     62
#define NP     93
#define P2     96        // padded proxies
#define NA     2730      // anchors 0,3,...,8187
#define EPSV   1e-6f
#define EPS2T  1.28e-10f // ZD*EPS^2
#define SZP    132       // padded smem z row (floats)
#define DTHR   256       // k_dist threads (8 warps; warp = 8 samples x 96 proxies)
#define HB_W   8
#define HGRID  ((NA + HB_W - 1) / HB_W)   // 342

#define SMEM_Z_FLOATS  (64 * SZP)     // 8448
#define SMEM_P_FLOATS  (ZD * P2)      // 12288
#define SMEM_DYN_BYTES ((SMEM_Z_FLOATS + SMEM_P_FLOATS) * 4)   // 82944

// ---------------- persistent scratch (device globals, zero-init) -------------
__device__ int   g_clsidx[BN];
__device__ int2  g_ab[NA];             // per-anchor class-list [lo,hi)
__device__ int   g_pidx[NA];           // nearest proxy per anchor
__device__ float g_Dpz[P2 * BN];       // dist(proxy p, z j), eps sign psum-zs
__device__ float g_DT [BN * P2];       // dist(z j, proxy p), eps sign zs-psum
__device__ float g_loss[NA];
__device__ unsigned int g_done;

// ---------------- helpers ---------------------------------------------------
__device__ __forceinline__ float warp_sum(float v) {
#pragma unroll
    for (int o = 16; o; o >>= 1) v += __shfl_xor_sync(0xffffffffu, v, o);
    return v;
}
__device__ __forceinline__ void warp_argmin(float& v, int& i) {
#pragma unroll
    for (int o = 16; o; o >>= 1) {
        float v2 = __shfl_xor_sync(0xffffffffu, v, o);
        int   i2 = __shfl_xor_sync(0xffffffffu, i, o);
        if (v2 < v || (v2 == v && i2 < i)) { v = v2; i = i2; }
    }
}
__device__ __forceinline__ void warp_argmax(float& v, int& i) {
#pragma unroll
    for (int o = 16; o; o >>= 1) {
        float v2 = __shfl_xor_sync(0xffffffffu, v, o);
        int   i2 = __shfl_xor_sync(0xffffffffu, i, o);
        if (v2 > v || (v2 == v && i2 < i)) { v = v2; i = i2; }
    }
}

// ============ K1: distances + nearest-proxy + class lists ====================
// grid: 129 x 256. Blocks 0..127: 96x64 tiles (self-contained: per-block proxy
// normalize into smem; broadcast-z mainloop). Block 128: scatter + g_ab.
__global__ void __launch_bounds__(DTHR) k_dist(const float* __restrict__ z,
                                               const int* __restrict__ y_idx,
                                               const int* __restrict__ y_map,
                                               const float* __restrict__ proxies) {
    extern __shared__ float smem[];
    float* s_z   = smem;                  // [64][SZP]
    float* s_prx = smem + SMEM_Z_FLOATS;  // [ZD][P2]
    __shared__ float s_zz[64], s_zs[64];
    __shared__ float s_pss[P2], s_psum[P2];

    int b = blockIdx.x, t = threadIdx.x;
    int w = t >> 5, lane = t & 31;

    if (b == 128) {    // ---- service: y_rel + scatter + per-anchor bounds ----
        __shared__ int s_inv[NC];
        __shared__ int cnt[NC], cur[NC], start[NC + 1];
        if (t < NC) { s_inv[y_map[t]] = t; cnt[t] = 0; }
        __syncthreads();
        for (int j = t; j < BN; j += DTHR) atomicAdd(&cnt[s_inv[y_idx[j]]], 1);
        __syncthreads();
        if (t == 0) {
            int acc = 0;
            for (int c = 0; c < NC; c++) { start[c] = acc; acc += cnt[c]; }
            start[NC] = acc;
        }
        __syncthreads();
        if (t < NC) cur[t] = start[t];
        __syncthreads();
        for (int j = t; j < BN; j += DTHR) {
            int c = s_inv[y_idx[j]];
            int pos = atomicAdd(&cur[c], 1);
            g_clsidx[pos] = j;
        }
        for (int i = t; i < NA; i += DTHR) {
            int c = s_inv[y_idx[3 * i]];
            g_ab[i] = make_int2(start[c], start[c + 1]);
        }
        return;
    }

    // ---- stage 64 z rows (warp-aligned stride -> free per-row stats) ----
    int B0 = b * 64;
    const float4* z4 = (const float4*)z;
    for (int idx = t; idx < 64 * 32; idx += DTHR) {
        int r = idx >> 5, q = idx & 31;          // r warp-uniform
        float4 v = z4[(size_t)(B0 + r) * 32 + q];
        float* dst = &s_z[r * SZP + 4 * q];
        dst[0] = v.x; dst[1] = v.y; dst[2] = v.z; dst[3] = v.w;
        float s  = (v.x + v.y) + (v.z + v.w);
        float ss = (v.x * v.x + v.y * v.y) + (v.z * v.z + v.w * v.w);
#pragma unroll
        for (int o = 16; o; o >>= 1) {
            s  += __shfl_xor_sync(0xffffffffu, s, o);
            ss += __shfl_xor_sync(0xffffffffu, ss, o);
        }
        if (lane == 0) { s_zs[r] = s; s_zz[r] = ss; }
    }
    // ---- normalize proxies into smem [k][p] (warp per proxy, 8 warps) ----
    for (int p = w; p < NP; p += 8) {
        float4 v = ((const float4*)(proxies + p * ZD))[lane];
        float ss = warp_sum(v.x * v.x + v.y * v.y + v.z * v.z + v.w * v.w);
        float inv = 1.f / fmaxf(sqrtf(ss), 1e-12f);
        float4 o = make_float4(v.x * inv, v.y * inv, v.z * inv, v.w * inv);
        int k0 = 4 * lane;
        s_prx[(k0 + 0) * P2 + p] = o.x;
        s_prx[(k0 + 1) * P2 + p] = o.y;
        s_prx[(k0 + 2) * P2 + p] = o.z;
        s_prx[(k0 + 3) * P2 + p] = o.w;
        float so  = warp_sum(o.x + o.y + o.z + o.w);
        float so2 = warp_sum(o.x * o.x + o.y * o.y + o.z * o.z + o.w * o.w);
        if (lane == 0) { s_psum[p] = so; s_pss[p] = so2; }
    }
    // zero proxy pad columns + pad stats
    for (int idx = t; idx < ZD * 3; idx += DTHR)
        s_prx[(idx / 3) * P2 + NP + (idx % 3)] = 0.f;
    if (t >= NP && t < P2) { s_pss[t] = 0.f; s_psum[t] = 0.f; }
    __syncthreads();

    // ---- mainloop: warp = samples [8w,8w+8) x all 96 proxies ----
    // lane owns proxies p = lane, lane+32, lane+64. z reads are broadcasts.
    int sl = 8 * w;                       // warp's local sample base
    const float* zrow0 = &s_z[(sl + 0) * SZP];
    const float* zrow1 = &s_z[(sl + 1) * SZP];
    const float* zrow2 = &s_z[(sl + 2) * SZP];
    const float* zrow3 = &s_z[(sl + 3) * SZP];
    const float* zrow4 = &s_z[(sl + 4) * SZP];
    const float* zrow5 = &s_z[(sl + 5) * SZP];
    const float* zrow6 = &s_z[(sl + 6) * SZP];
    const float* zrow7 = &s_z[(sl + 7) * SZP];

    float acc[3][8];
#pragma unroll
    for (int q = 0; q < 3; q++)
#pragma unroll
        for (int i = 0; i < 8; i++) acc[q][i] = 0.f;

#pragma unroll 4
    for (int k = 0; k < ZD; k++) {
        float pv0 = s_prx[k * P2 + lane];        // conflict-free
        float pv1 = s_prx[k * P2 + lane + 32];
        float pv2 = s_prx[k * P2 + lane + 64];
        float z0 = zrow0[k], z1 = zrow1[k], z2 = zrow2[k], z3 = zrow3[k];
        float z4v = zrow4[k], z5 = zrow5[k], z6 = zrow6[k], z7 = zrow7[k];
        acc[0][0] = fmaf(pv0, z0, acc[0][0]); acc[0][1] = fmaf(pv0, z1, acc[0][1]);
        acc[0][2] = fmaf(pv0, z2, acc[0][2]); acc[0][3] = fmaf(pv0, z3, acc[0][3]);
        acc[0][4] = fmaf(pv0, z4v, acc[0][4]); acc[0][5] = fmaf(pv0, z5, acc[0][5]);
        acc[0][6] = fmaf(pv0, z6, acc[0][6]); acc[0][7] = fmaf(pv0, z7, acc[0][7]);
        acc[1][0] = fmaf(pv1, z0, acc[1][0]); acc[1][1] = fmaf(pv1, z1, acc[1][1]);
        acc[1][2] = fmaf(pv1, z2, acc[1][2]); acc[1][3] = fmaf(pv1, z3, acc[1][3]);
        acc[1][4] = fmaf(pv1, z4v, acc[1][4]); acc[1][5] = fmaf(pv1, z5, acc[1][5]);
        acc[1][6] = fmaf(pv1, z6, acc[1][6]); acc[1][7] = fmaf(pv1, z7, acc[1][7]);
        acc[2][0] = fmaf(pv2, z0, acc[2][0]); acc[2][1] = fmaf(pv2, z1, acc[2][1]);
        acc[2][2] = fmaf(pv2, z2, acc[2][2]); acc[2][3] = fmaf(pv2, z3, acc[2][3]);
        acc[2][4] = fmaf(pv2, z4v, acc[2][4]); acc[2][5] = fmaf(pv2, z5, acc[2][5]);
        acc[2][6] = fmaf(pv2, z6, acc[2][6]); acc[2][7] = fmaf(pv2, z7, acc[2][7]);
    }

    // ---- epilogue: per sample, distances + stores + anchor argmin ----
    float pss0 = s_pss[lane],      psm0 = s_psum[lane];
    float pss1 = s_pss[lane + 32], psm1 = s_psum[lane + 32];
    float pss2 = s_pss[lane + 64], psm2 = s_psum[lane + 64];

#pragma unroll
    for (int i = 0; i < 8; i++) {
        int sglob = B0 + sl + i;
        float zzv = s_zz[sl + i], zsv = s_zs[sl + i];
        float base0 = zzv + pss0 - 2.f * acc[0][i];
        float base1 = zzv + pss1 - 2.f * acc[1][i];
        float base2 = zzv + pss2 - 2.f * acc[2][i];
        float e0 = 2.f * EPSV * (psm0 - zsv);
        float e1 = 2.f * EPSV * (psm1 - zsv);
        float e2 = 2.f * EPSV * (psm2 - zsv);
        float dpz0 = sqrtf(fmaxf(base0 + e0 + EPS2T, 0.f));
        float dpz1 = sqrtf(fmaxf(base1 + e1 + EPS2T, 0.f));
        float dpz2 = sqrtf(fmaxf(base2 + e2 + EPS2T, 0.f));
        float dzp0 = sqrtf(fmaxf(base0 - e0 + EPS2T, 0.f));
        float dzp1 = sqrtf(fmaxf(base1 - e1 + EPS2T, 0.f));
        float dzp2 = sqrtf(fmaxf(base2 - e2 + EPS2T, 0.f));

        // Dpz: column writes (scattered across rows; L2 absorbs)
        g_Dpz[(size_t)(lane)      * BN + sglob] = dpz0;
        g_Dpz[(size_t)(lane + 32) * BN + sglob] = dpz1;
        g_Dpz[(size_t)(lane + 64) * BN + sglob] = dpz2;
        // DT: coalesced row writes
        float* dt = g_DT + (size_t)sglob * P2;
        dt[lane] = dzp0; dt[lane + 32] = dzp1; dt[lane + 64] = dzp2;

        // nearest-proxy argmin for anchor rows
        if (sglob % 3 == 0 && sglob / 3 < NA) {
            float bv = dzp0; int bp = lane;                    // p ascending
            if (lane + 32 < NP && dzp1 < bv) { bv = dzp1; bp = lane + 32; }
            if (lane + 64 < NP && dzp2 < bv) { bv = dzp2; bp = lane + 64; }
            warp_argmin(bv, bp);
            if (lane == 0) g_pidx[sglob / 3] = bp;
        }
    }
}

// ============ K2: warp-per-anchor: hardpos + lse + mean ======================
// grid: HGRID x 256
__global__ void __launch_bounds__(256) k_hard(float* __restrict__ out) {
    __shared__ float rbuf[8];
    __shared__ int s_last;
    int t = threadIdx.x, w = t >> 5, lane = t & 31;
    int i = blockIdx.x * HB_W + w;

    if (i < NA) {
        int a = 3 * i;
        int px = g_pidx[i];
        int2 ab = g_ab[i];
        const float* Drow = g_Dpz + (size_t)px * BN;
        float hb = -INFINITY; int hj = 0x7fffffff;
        for (int idx = ab.x + lane; idx < ab.y; idx += 64) {
            int j0 = g_clsidx[idx];
            int i2 = idx + 32;
            int j1 = (i2 < ab.y) ? g_clsidx[i2] : -1;
            if (j0 >= a) {
                float d = __ldg(Drow + j0);
                if (d > hb || (d == hb && j0 < hj)) { hb = d; hj = j0; }
            }
            if (j1 >= a) {
                float d = __ldg(Drow + j1);
                if (d > hb || (d == hb && j1 < hj)) { hb = d; hj = j1; }
            }
        }
        warp_argmax(hb, hj);                 // hj = j_p, hb = D_p

        const float* dtj = g_DT + (size_t)hj * P2;
        float nd0 = (lane      < NP) ? -__ldg(dtj + lane)      : -INFINITY;
        float nd1 = (lane + 32 < NP) ? -__ldg(dtj + lane + 32) : -INFINITY;
        float nd2 = (lane + 64 < NP) ? -__ldg(dtj + lane + 64) : -INFINITY;
        float m = fmaxf(nd0, fmaxf(nd1, nd2));
#pragma unroll
        for (int o = 16; o; o >>= 1) m = fmaxf(m, __shfl_xor_sync(0xffffffffu, m, o));
        float s = expf(nd0 - m) + expf(nd1 - m) + expf(nd2 - m);
        s = warp_sum(s);
        if (lane == 0) g_loss[i] = hb + (m + logf(s));
    }

    // ---- last block: deterministic mean ----
    __threadfence();
    __syncthreads();
    if (t == 0) s_last = (atomicAdd(&g_done, 1u) == (unsigned)(gridDim.x - 1));
    __syncthreads();
    if (s_last) {
        __threadfence();
        float s = 0.f;
        for (int k = t; k < NA; k += 256) s += g_loss[k];
        s = warp_sum(s);
        if (lane == 0) rbuf[w] = s;
        __syncthreads();
        if (t == 0) {
            float total = 0.f;
#pragma unroll
            for (int q = 0; q < 8; q++) total += rbuf[q];
            out[0] = total / (float)NA;
            g_done = 0;
        }
    }
}

// ---------------- launch ------------------------------------------------------
extern "C" void kernel_launch(void* const* d_in, const int* in_sizes, int n_in,
                              void* d_out, int out_size) {
    const float* z       = (const float*)d_in[0];
    const int*   y_idx   = (const int*)d_in[1];
    const float* proxies = (const float*)d_in[2];
    const int*   y_map   = (const int*)d_in[3];
    float*       out     = (float*)d_out;

    cudaFuncSetAttribute(k_dist, cudaFuncAttributeMaxDynamicSharedMemorySize,
                         SMEM_DYN_BYTES);
    k_dist<<<129, DTHR, SMEM_DYN_BYTES>>>(z, y_idx, y_map, proxies);
    k_hard<<<HGRID, 256>>>(out);
}

// round 10
// speedup vs baseline: 1.7196x; 1.2892x over previous
#include <cuda_runtime.h>
#include <cuda_bf16.h>
#include <math.h>

#define BN     8192
#define ZD     128
#define NC     62
#define NP     93
#define P2     96        // padded proxies
#define NA     2730      // anchors 0,3,...,8187
#define EPSV   1e-6f
#define EPS2T  1.28e-10f // ZD*EPS^2
#define SZP    132       // padded smem row pitch (floats) for z AND prx
#define SDP    68        // padded dpz-transpose pitch
#define DTHR   256       // 8 warps; warp = 8 samples x 96 proxies
#define HB_W   8
#define HGRID  ((NA + HB_W - 1) / HB_W)   // 342

#define SMEM_Z_FLOATS  (64 * SZP)     // 8448  (also overlaid by s_dpz 96*68=6528)
#define SMEM_P_FLOATS  (P2 * SZP)     // 12672
#define SMEM_DYN_BYTES ((SMEM_Z_FLOATS + SMEM_P_FLOATS) * 4)   // 84480

// ---------------- persistent scratch (device globals, zero-init) -------------
__device__ int   g_clsidx[BN];
__device__ int2  g_ab[NA];             // per-anchor class-list [lo,hi)
__device__ int   g_pidx[NA];           // nearest proxy per anchor
__device__ float g_Dpz[P2 * BN];       // dist(proxy p, z j), eps sign psum-zs
__device__ float g_DT [BN * P2];       // dist(z j, proxy p), eps sign zs-psum
__device__ float g_loss[NA];
__device__ unsigned int g_done;

// ---------------- helpers ---------------------------------------------------
__device__ __forceinline__ float warp_sum(float v) {
#pragma unroll
    for (int o = 16; o; o >>= 1) v += __shfl_xor_sync(0xffffffffu, v, o);
    return v;
}
__device__ __forceinline__ void warp_argmin(float& v, int& i) {
#pragma unroll
    for (int o = 16; o; o >>= 1) {
        float v2 = __shfl_xor_sync(0xffffffffu, v, o);
        int   i2 = __shfl_xor_sync(0xffffffffu, i, o);
        if (v2 < v || (v2 == v && i2 < i)) { v = v2; i = i2; }
    }
}
__device__ __forceinline__ void warp_argmax(float& v, int& i) {
#pragma unroll
    for (int o = 16; o; o >>= 1) {
        float v2 = __shfl_xor_sync(0xffffffffu, v, o);
        int   i2 = __shfl_xor_sync(0xffffffffu, i, o);
        if (v2 > v || (v2 == v && i2 < i)) { v = v2; i = i2; }
    }
}

// ============ K1: distances + nearest-proxy + class lists ====================
// grid: 129 x 256. Blocks 0..127: 96x64 tiles. Block 128: scatter + g_ab.
__global__ void __launch_bounds__(DTHR) k_dist(const float* __restrict__ z,
                                               const int* __restrict__ y_idx,
                                               const int* __restrict__ y_map,
                                               const float* __restrict__ proxies) {
    extern __shared__ float smem[];
    float* s_z   = smem;                  // [64][SZP]; reused as s_dpz[96][SDP]
    float* s_prx = smem + SMEM_Z_FLOATS;  // [P2][SZP]  row-major [p][k]
    __shared__ float s_zz[64], s_zs[64];
    __shared__ float s_pss[P2], s_psum[P2];

    int b = blockIdx.x, t = threadIdx.x;
    int w = t >> 5, lane = t & 31;

    if (b == 128) {    // ---- service: y_rel + scatter + per-anchor bounds ----
        __shared__ int s_inv[NC];
        __shared__ int cnt[NC], cur[NC], start[NC + 1];
        if (t < NC) { s_inv[y_map[t]] = t; cnt[t] = 0; }
        __syncthreads();
        for (int j = t; j < BN; j += DTHR) atomicAdd(&cnt[s_inv[y_idx[j]]], 1);
        __syncthreads();
        if (t == 0) {
            int acc = 0;
            for (int c = 0; c < NC; c++) { start[c] = acc; acc += cnt[c]; }
            start[NC] = acc;
        }
        __syncthreads();
        if (t < NC) cur[t] = start[t];
        __syncthreads();
        for (int j = t; j < BN; j += DTHR) {
            int c = s_inv[y_idx[j]];
            int pos = atomicAdd(&cur[c], 1);
            g_clsidx[pos] = j;
        }
        for (int i = t; i < NA; i += DTHR) {
            int c = s_inv[y_idx[3 * i]];
            g_ab[i] = make_int2(start[c], start[c + 1]);
        }
        return;
    }

    // ---- stage 64 z rows (warp-aligned stride -> free per-row stats) ----
    int B0 = b * 64;
    const float4* z4 = (const float4*)z;
    for (int idx = t; idx < 64 * 32; idx += DTHR) {
        int r = idx >> 5, q = idx & 31;          // r warp-uniform
        float4 v = z4[(size_t)(B0 + r) * 32 + q];
        *(float4*)&s_z[r * SZP + 4 * q] = v;
        float s  = (v.x + v.y) + (v.z + v.w);
        float ss = (v.x * v.x + v.y * v.y) + (v.z * v.z + v.w * v.w);
#pragma unroll
        for (int o = 16; o; o >>= 1) {
            s  += __shfl_xor_sync(0xffffffffu, s, o);
            ss += __shfl_xor_sync(0xffffffffu, ss, o);
        }
        if (lane == 0) { s_zs[r] = s; s_zz[r] = ss; }
    }
    // ---- normalize proxies into smem [p][k] (warp per proxy, 8 warps) ----
    for (int p = w; p < NP; p += 8) {
        float4 v = ((const float4*)(proxies + p * ZD))[lane];
        float ss = warp_sum(v.x * v.x + v.y * v.y + v.z * v.z + v.w * v.w);
        float inv = 1.f / fmaxf(sqrtf(ss), 1e-12f);
        float4 o = make_float4(v.x * inv, v.y * inv, v.z * inv, v.w * inv);
        *(float4*)&s_prx[p * SZP + 4 * lane] = o;
        float so  = warp_sum(o.x + o.y + o.z + o.w);
        float so2 = warp_sum(o.x * o.x + o.y * o.y + o.z * o.z + o.w * o.w);
        if (lane == 0) { s_psum[p] = so; s_pss[p] = so2; }
    }
    // zero pad proxy rows 93..95 + pad stats
    for (int idx = t; idx < 3 * 32; idx += DTHR)
        *(float4*)&s_prx[(NP + idx / 32) * SZP + 4 * (idx % 32)] =
            make_float4(0.f, 0.f, 0.f, 0.f);
    if (t >= NP && t < P2) { s_pss[t] = 0.f; s_psum[t] = 0.f; }
    __syncthreads();

    // ---- mainloop: warp = samples [8w,8w+8) x 96 proxies, float4 over k ----
    int sl = 8 * w;
    const float* pr0 = &s_prx[(lane)      * SZP];
    const float* pr1 = &s_prx[(lane + 32) * SZP];
    const float* pr2 = &s_prx[(lane + 64) * SZP];
    const float* zr[8];
#pragma unroll
    for (int i = 0; i < 8; i++) zr[i] = &s_z[(sl + i) * SZP];

    float acc[3][8];
#pragma unroll
    for (int q = 0; q < 3; q++)
#pragma unroll
        for (int i = 0; i < 8; i++) acc[q][i] = 0.f;

#pragma unroll 2
    for (int k4 = 0; k4 < 32; k4++) {
        int ko = 4 * k4;
        float4 p0 = *(const float4*)&pr0[ko];   // conflict-free (132-pitch)
        float4 p1 = *(const float4*)&pr1[ko];
        float4 p2 = *(const float4*)&pr2[ko];
#pragma unroll
        for (int i = 0; i < 8; i++) {
            float4 zv = *(const float4*)&zr[i][ko];   // broadcast
            acc[0][i] = fmaf(p0.x, zv.x, acc[0][i]);
            acc[0][i] = fmaf(p0.y, zv.y, acc[0][i]);
            acc[0][i] = fmaf(p0.z, zv.z, acc[0][i]);
            acc[0][i] = fmaf(p0.w, zv.w, acc[0][i]);
            acc[1][i] = fmaf(p1.x, zv.x, acc[1][i]);
            acc[1][i] = fmaf(p1.y, zv.y, acc[1][i]);
            acc[1][i] = fmaf(p1.z, zv.z, acc[1][i]);
            acc[1][i] = fmaf(p1.w, zv.w, acc[1][i]);
            acc[2][i] = fmaf(p2.x, zv.x, acc[2][i]);
            acc[2][i] = fmaf(p2.y, zv.y, acc[2][i]);
            acc[2][i] = fmaf(p2.z, zv.z, acc[2][i]);
            acc[2][i] = fmaf(p2.w, zv.w, acc[2][i]);
        }
    }

    // ---- epilogue: distances; DT rows direct; Dpz via smem transpose ----
    float pss0 = s_pss[lane],      psm0 = s_psum[lane];
    float pss1 = s_pss[lane + 32], psm1 = s_psum[lane + 32];
    float pss2 = s_pss[lane + 64], psm2 = s_psum[lane + 64];
    float zzv[8], zsv[8];
#pragma unroll
    for (int i = 0; i < 8; i++) { zzv[i] = s_zz[sl + i]; zsv[i] = s_zs[sl + i]; }

    float dpzv[3][8];
    __syncthreads();                       // all mainloop smem reads done
    float* s_dpz = s_z;                    // overlay: [96][SDP]

#pragma unroll
    for (int i = 0; i < 8; i++) {
        int sglob = B0 + sl + i;
        float base0 = zzv[i] + pss0 - 2.f * acc[0][i];
        float base1 = zzv[i] + pss1 - 2.f * acc[1][i];
        float base2 = zzv[i] + pss2 - 2.f * acc[2][i];
        float e0 = 2.f * EPSV * (psm0 - zsv[i]);
        float e1 = 2.f * EPSV * (psm1 - zsv[i]);
        float e2 = 2.f * EPSV * (psm2 - zsv[i]);
        dpzv[0][i] = sqrtf(fmaxf(base0 + e0 + EPS2T, 0.f));
        dpzv[1][i] = sqrtf(fmaxf(base1 + e1 + EPS2T, 0.f));
        dpzv[2][i] = sqrtf(fmaxf(base2 + e2 + EPS2T, 0.f));
        float dzp0 = sqrtf(fmaxf(base0 - e0 + EPS2T, 0.f));
        float dzp1 = sqrtf(fmaxf(base1 - e1 + EPS2T, 0.f));
        float dzp2 = sqrtf(fmaxf(base2 - e2 + EPS2T, 0.f));

        // DT: coalesced row writes
        float* dt = g_DT + (size_t)sglob * P2;
        dt[lane] = dzp0; dt[lane + 32] = dzp1; dt[lane + 64] = dzp2;

        // dpz into transpose buffer (pitch 68 -> conflict-free phases)
        int sc = sl + i;
        s_dpz[(lane)      * SDP + sc] = dpzv[0][i];
        s_dpz[(lane + 32) * SDP + sc] = dpzv[1][i];
        s_dpz[(lane + 64) * SDP + sc] = dpzv[2][i];

        // nearest-proxy argmin for anchor rows (dzp in registers)
        if (sglob % 3 == 0 && sglob / 3 < NA) {
            float bv = dzp0; int bp = lane;
            if (lane + 32 < NP && dzp1 < bv) { bv = dzp1; bp = lane + 32; }
            if (lane + 64 < NP && dzp2 < bv) { bv = dzp2; bp = lane + 64; }
            warp_argmin(bv, bp);
            if (lane == 0) g_pidx[sglob / 3] = bp;
        }
    }
    __syncthreads();

    // coalesced Dpz row writes: 96 rows x 64 floats
    for (int idx = t; idx < 96 * 16; idx += DTHR) {
        int p = idx >> 4, q = idx & 15;
        float4 v = make_float4(s_dpz[p * SDP + 4 * q],     s_dpz[p * SDP + 4 * q + 1],
                               s_dpz[p * SDP + 4 * q + 2], s_dpz[p * SDP + 4 * q + 3]);
        *(float4*)(g_Dpz + (size_t)p * BN + B0 + 4 * q) = v;
    }
}

// ============ K2: warp-per-anchor: hardpos + lse + mean ======================
// grid: HGRID x 256
__global__ void __launch_bounds__(256) k_hard(float* __restrict__ out) {
    __shared__ float rbuf[8];
    __shared__ int s_last;
    int t = threadIdx.x, w = t >> 5, lane = t & 31;
    int i = blockIdx.x * HB_W + w;

    if (i < NA) {
        int a = 3 * i;
        int px = g_pidx[i];
        int2 ab = g_ab[i];
        const float* Drow = g_Dpz + (size_t)px * BN;
        float hb = -INFINITY; int hj = 0x7fffffff;
        for (int idx = ab.x + lane; idx < ab.y; idx += 64) {
            int j0 = g_clsidx[idx];
            int i2 = idx + 32;
            int j1 = (i2 < ab.y) ? g_clsidx[i2] : -1;
            if (j0 >= a) {
                float d = __ldg(Drow + j0);
                if (d > hb || (d == hb && j0 < hj)) { hb = d; hj = j0; }
            }
            if (j1 >= a) {
                float d = __ldg(Drow + j1);
                if (d > hb || (d == hb && j1 < hj)) { hb = d; hj = j1; }
            }
        }
        warp_argmax(hb, hj);                 // hj = j_p, hb = D_p

        const float* dtj = g_DT + (size_t)hj * P2;
        float nd0 = (lane      < NP) ? -__ldg(dtj + lane)      : -INFINITY;
        float nd1 = (lane + 32 < NP) ? -__ldg(dtj + lane + 32) : -INFINITY;
        float nd2 = (lane + 64 < NP) ? -__ldg(dtj + lane + 64) : -INFINITY;
        float m = fmaxf(nd0, fmaxf(nd1, nd2));
#pragma unroll
        for (int o = 16; o; o >>= 1) m = fmaxf(m, __shfl_xor_sync(0xffffffffu, m, o));
        float s = expf(nd0 - m) + expf(nd1 - m) + expf(nd2 - m);
        s = warp_sum(s);
        if (lane == 0) g_loss[i] = hb + (m + logf(s));
    }

    // ---- last block: deterministic mean ----
    __threadfence();
    __syncthreads();
    if (t == 0) s_last = (atomicAdd(&g_done, 1u) == (unsigned)(gridDim.x - 1));
    __syncthreads();
    if (s_last) {
        __threadfence();
        float s = 0.f;
        for (int k = t; k < NA; k += 256) s += g_loss[k];
        s = warp_sum(s);
        if (lane == 0) rbuf[w] = s;
        __syncthreads();
        if (t == 0) {
            float total = 0.f;
#pragma unroll
            for (int q = 0; q < 8; q++) total += rbuf[q];
            out[0] = total / (float)NA;
            g_done = 0;
        }
    }
}

// ---------------- launch ------------------------------------------------------
extern "C" void kernel_launch(void* const* d_in, const int* in_sizes, int n_in,
                              void* d_out, int out_size) {
    const float* z       = (const float*)d_in[0];
    const int*   y_idx   = (const int*)d_in[1];
    const float* proxies = (const float*)d_in[2];
    const int*   y_map   = (const int*)d_in[3];
    float*       out     = (float*)d_out;

    cudaFuncSetAttribute(k_dist, cudaFuncAttributeMaxDynamicSharedMemorySize,
                         SMEM_DYN_BYTES);
    k_dist<<<129, DTHR, SMEM_DYN_BYTES>>>(z, y_idx, y_map, proxies);
    k_hard<<<HGRID, 256>>>(out);
}

// round 11
// speedup vs baseline: 1.9823x; 1.1528x over previous
#include <cuda_runtime.h>
#include <cuda_bf16.h>
#include <math.h>

#define BN     8192
#define ZD     128
#define NC     62
#define NP     93
#define P2     96        // padded proxies
#define NA     2730      // anchors 0,3,...,8187
#define EPSV   1e-6f
#define EPS2T  1.28e-10f // ZD*EPS^2
#define SZP    132       // padded smem row pitch (floats) for z AND prx
#define SDP    68        // padded dpz-transpose pitch
#define DTHR   512       // 16 warps; warp = 4 samples x 96 proxies
#define HB_W   8
#define HGRID  ((NA + HB_W - 1) / HB_W)   // 342

#define SMEM_Z_FLOATS  (64 * SZP)     // 8448 (overlaid by s_dpz 96*68=6528)
#define SMEM_P_FLOATS  (P2 * SZP)     // 12672
#define SMEM_DYN_BYTES ((SMEM_Z_FLOATS + SMEM_P_FLOATS) * 4)   // 84480

// ---------------- persistent scratch (device globals, zero-init) -------------
__device__ int   g_clsidx[BN];
__device__ int2  g_ab[NA];             // per-anchor class-list [lo,hi)
__device__ int   g_pidx[NA];           // nearest proxy per anchor
__device__ float g_Dpz[P2 * BN];       // dist(proxy p, z j), eps sign psum-zs
__device__ float g_DT [BN * P2];       // dist(z j, proxy p), eps sign zs-psum
__device__ float g_loss[NA];
__device__ unsigned int g_done;

// ---------------- helpers ---------------------------------------------------
__device__ __forceinline__ float warp_sum(float v) {
#pragma unroll
    for (int o = 16; o; o >>= 1) v += __shfl_xor_sync(0xffffffffu, v, o);
    return v;
}
__device__ __forceinline__ void warp_argmin(float& v, int& i) {
#pragma unroll
    for (int o = 16; o; o >>= 1) {
        float v2 = __shfl_xor_sync(0xffffffffu, v, o);
        int   i2 = __shfl_xor_sync(0xffffffffu, i, o);
        if (v2 < v || (v2 == v && i2 < i)) { v = v2; i = i2; }
    }
}
__device__ __forceinline__ void warp_argmax(float& v, int& i) {
#pragma unroll
    for (int o = 16; o; o >>= 1) {
        float v2 = __shfl_xor_sync(0xffffffffu, v, o);
        int   i2 = __shfl_xor_sync(0xffffffffu, i, o);
        if (v2 > v || (v2 == v && i2 < i)) { v = v2; i = i2; }
    }
}

// ============ K1: distances + nearest-proxy + class lists ====================
// grid: 129 x 512. Blocks 0..127: 96x64 tiles. Block 128: scatter + g_ab.
__global__ void __launch_bounds__(DTHR) k_dist(const float* __restrict__ z,
                                               const int* __restrict__ y_idx,
                                               const int* __restrict__ y_map,
                                               const float* __restrict__ proxies) {
    extern __shared__ float smem[];
    float* s_z   = smem;                  // [64][SZP]; reused as s_dpz[96][SDP]
    float* s_prx = smem + SMEM_Z_FLOATS;  // [P2][SZP]  row-major [p][k]
    __shared__ float s_zz[64], s_zs[64];
    __shared__ float s_pss[P2], s_psum[P2];

    int b = blockIdx.x, t = threadIdx.x;
    int w = t >> 5, lane = t & 31;

    if (b == 128) {    // ---- service: y_rel + scatter + per-anchor bounds ----
        __shared__ int s_inv[NC];
        __shared__ int cnt[NC], cur[NC], start[NC + 1];
        if (t < NC) { s_inv[y_map[t]] = t; cnt[t] = 0; }
        __syncthreads();
        for (int j = t; j < BN; j += DTHR) atomicAdd(&cnt[s_inv[y_idx[j]]], 1);
        __syncthreads();
        if (t == 0) {
            int acc = 0;
            for (int c = 0; c < NC; c++) { start[c] = acc; acc += cnt[c]; }
            start[NC] = acc;
        }
        __syncthreads();
        if (t < NC) cur[t] = start[t];
        __syncthreads();
        for (int j = t; j < BN; j += DTHR) {
            int c = s_inv[y_idx[j]];
            int pos = atomicAdd(&cur[c], 1);
            g_clsidx[pos] = j;
        }
        for (int i = t; i < NA; i += DTHR) {
            int c = s_inv[y_idx[3 * i]];
            g_ab[i] = make_int2(start[c], start[c + 1]);
        }
        return;
    }

    // ---- stage 64 z rows (warp-aligned stride -> free per-row stats) ----
    int B0 = b * 64;
    const float4* z4 = (const float4*)z;
    for (int idx = t; idx < 64 * 32; idx += DTHR) {
        int r = idx >> 5, q = idx & 31;          // r warp-uniform
        float4 v = z4[(size_t)(B0 + r) * 32 + q];
        *(float4*)&s_z[r * SZP + 4 * q] = v;
        float s  = (v.x + v.y) + (v.z + v.w);
        float ss = (v.x * v.x + v.y * v.y) + (v.z * v.z + v.w * v.w);
#pragma unroll
        for (int o = 16; o; o >>= 1) {
            s  += __shfl_xor_sync(0xffffffffu, s, o);
            ss += __shfl_xor_sync(0xffffffffu, ss, o);
        }
        if (lane == 0) { s_zs[r] = s; s_zz[r] = ss; }
    }
    // ---- normalize proxies into smem [p][k] (warp per proxy, 16 warps) ----
    for (int p = w; p < NP; p += 16) {
        float4 v = ((const float4*)(proxies + p * ZD))[lane];
        float ss = warp_sum(v.x * v.x + v.y * v.y + v.z * v.z + v.w * v.w);
        float inv = 1.f / fmaxf(sqrtf(ss), 1e-12f);
        float4 o = make_float4(v.x * inv, v.y * inv, v.z * inv, v.w * inv);
        *(float4*)&s_prx[p * SZP + 4 * lane] = o;
        float so  = warp_sum(o.x + o.y + o.z + o.w);
        float so2 = warp_sum(o.x * o.x + o.y * o.y + o.z * o.z + o.w * o.w);
        if (lane == 0) { s_psum[p] = so; s_pss[p] = so2; }
    }
    // zero pad proxy rows 93..95 + pad stats
    for (int idx = t; idx < 3 * 32; idx += DTHR)
        *(float4*)&s_prx[(NP + idx / 32) * SZP + 4 * (idx % 32)] =
            make_float4(0.f, 0.f, 0.f, 0.f);
    if (t >= NP && t < P2) { s_pss[t] = 0.f; s_psum[t] = 0.f; }
    __syncthreads();

    // ---- mainloop: warp = samples [4w,4w+4) x 96 proxies, float4 over k ----
    int sl = 4 * w;
    const float* pr0 = &s_prx[(lane)      * SZP];
    const float* pr1 = &s_prx[(lane + 32) * SZP];
    const float* pr2 = &s_prx[(lane + 64) * SZP];
    const float* zr0 = &s_z[(sl + 0) * SZP];
    const float* zr1 = &s_z[(sl + 1) * SZP];
    const float* zr2 = &s_z[(sl + 2) * SZP];
    const float* zr3 = &s_z[(sl + 3) * SZP];

    float acc[3][4];
#pragma unroll
    for (int q = 0; q < 3; q++)
#pragma unroll
        for (int i = 0; i < 4; i++) acc[q][i] = 0.f;

#pragma unroll 4
    for (int k4 = 0; k4 < 32; k4++) {
        int ko = 4 * k4;
        float4 p0 = *(const float4*)&pr0[ko];   // conflict-free (132-pitch)
        float4 p1 = *(const float4*)&pr1[ko];
        float4 p2 = *(const float4*)&pr2[ko];
        float4 zv0 = *(const float4*)&zr0[ko];  // broadcasts
        float4 zv1 = *(const float4*)&zr1[ko];
        float4 zv2 = *(const float4*)&zr2[ko];
        float4 zv3 = *(const float4*)&zr3[ko];
#define DOT4(q, pv, i, zv) \
        acc[q][i] = fmaf(pv.x, zv.x, acc[q][i]); \
        acc[q][i] = fmaf(pv.y, zv.y, acc[q][i]); \
        acc[q][i] = fmaf(pv.z, zv.z, acc[q][i]); \
        acc[q][i] = fmaf(pv.w, zv.w, acc[q][i]);
        DOT4(0, p0, 0, zv0) DOT4(0, p0, 1, zv1) DOT4(0, p0, 2, zv2) DOT4(0, p0, 3, zv3)
        DOT4(1, p1, 0, zv0) DOT4(1, p1, 1, zv1) DOT4(1, p1, 2, zv2) DOT4(1, p1, 3, zv3)
        DOT4(2, p2, 0, zv0) DOT4(2, p2, 1, zv1) DOT4(2, p2, 2, zv2) DOT4(2, p2, 3, zv3)
#undef DOT4
    }

    // ---- epilogue: distances; DT rows direct; Dpz via smem transpose ----
    float pss0 = s_pss[lane],      psm0 = s_psum[lane];
    float pss1 = s_pss[lane + 32], psm1 = s_psum[lane + 32];
    float pss2 = s_pss[lane + 64], psm2 = s_psum[lane + 64];
    float zzv[4], zsv[4];
#pragma unroll
    for (int i = 0; i < 4; i++) { zzv[i] = s_zz[sl + i]; zsv[i] = s_zs[sl + i]; }

    __syncthreads();                       // all mainloop smem reads done
    float* s_dpz = s_z;                    // overlay: [96][SDP]

#pragma unroll
    for (int i = 0; i < 4; i++) {
        int sglob = B0 + sl + i;
        float base0 = zzv[i] + pss0 - 2.f * acc[0][i];
        float base1 = zzv[i] + pss1 - 2.f * acc[1][i];
        float base2 = zzv[i] + pss2 - 2.f * acc[2][i];
        float e0 = 2.f * EPSV * (psm0 - zsv[i]);
        float e1 = 2.f * EPSV * (psm1 - zsv[i]);
        float e2 = 2.f * EPSV * (psm2 - zsv[i]);
        float dpz0 = sqrtf(fmaxf(base0 + e0 + EPS2T, 0.f));
        float dpz1 = sqrtf(fmaxf(base1 + e1 + EPS2T, 0.f));
        float dpz2 = sqrtf(fmaxf(base2 + e2 + EPS2T, 0.f));
        float dzp0 = sqrtf(fmaxf(base0 - e0 + EPS2T, 0.f));
        float dzp1 = sqrtf(fmaxf(base1 - e1 + EPS2T, 0.f));
        float dzp2 = sqrtf(fmaxf(base2 - e2 + EPS2T, 0.f));

        // DT: coalesced row writes
        float* dt = g_DT + (size_t)sglob * P2;
        dt[lane] = dzp0; dt[lane + 32] = dzp1; dt[lane + 64] = dzp2;

        // dpz into transpose buffer
        int sc = sl + i;
        s_dpz[(lane)      * SDP + sc] = dpz0;
        s_dpz[(lane + 32) * SDP + sc] = dpz1;
        s_dpz[(lane + 64) * SDP + sc] = dpz2;

        // nearest-proxy argmin for anchor rows (dzp in registers)
        if (sglob % 3 == 0 && sglob / 3 < NA) {
            float bv = dzp0; int bp = lane;
            if (lane + 32 < NP && dzp1 < bv) { bv = dzp1; bp = lane + 32; }
            if (lane + 64 < NP && dzp2 < bv) { bv = dzp2; bp = lane + 64; }
            warp_argmin(bv, bp);
            if (lane == 0) g_pidx[sglob / 3] = bp;
        }
    }
    __syncthreads();

    // coalesced Dpz row writes: 96 rows x 64 floats
    for (int idx = t; idx < 96 * 16; idx += DTHR) {
        int p = idx >> 4, q = idx & 15;
        float4 v = make_float4(s_dpz[p * SDP + 4 * q],     s_dpz[p * SDP + 4 * q + 1],
                               s_dpz[p * SDP + 4 * q + 2], s_dpz[p * SDP + 4 * q + 3]);
        *(float4*)(g_Dpz + (size_t)p * BN + B0 + 4 * q) = v;
    }
}

// ============ K2: warp-per-anchor: hardpos + lse + mean ======================
// grid: HGRID x 256. Prefetched clsidx strips -> MLP 6 on the gather chain.
__global__ void __launch_bounds__(256) k_hard(float* __restrict__ out) {
    __shared__ float rbuf[8];
    __shared__ int s_last;
    int t = threadIdx.x, w = t >> 5, lane = t & 31;
    int i = blockIdx.x * HB_W + w;

    if (i < NA) {
        int a = 3 * i;
        int px = g_pidx[i];
        int2 ab = g_ab[i];
        const float* Drow = g_Dpz + (size_t)px * BN;

        // prefetch up to 6 strips of candidate indices (covers len <= 192)
        int jj[6];
#pragma unroll
        for (int q = 0; q < 6; q++) {
            int idx = ab.x + lane + 32 * q;
            jj[q] = (idx < ab.y) ? __ldg(g_clsidx + idx) : -1;
        }
        float hb = -INFINITY; int hj = 0x7fffffff;
#pragma unroll
        for (int q = 0; q < 6; q++) {
            int j = jj[q];
            if (j >= a) {
                float d = __ldg(Drow + j);
                if (d > hb || (d == hb && j < hj)) { hb = d; hj = j; }
            }
        }
        // safety tail (class size > 192: ~never, but correctness-guaranteed)
        for (int idx = ab.x + 192 + lane; idx < ab.y; idx += 32) {
            int j = __ldg(g_clsidx + idx);
            if (j >= a) {
                float d = __ldg(Drow + j);
                if (d > hb || (d == hb && j < hj)) { hb = d; hj = j; }
            }
        }
        warp_argmax(hb, hj);                 // hj = j_p, hb = D_p

        const float* dtj = g_DT + (size_t)hj * P2;
        float nd0 = (lane      < NP) ? -__ldg(dtj + lane)      : -INFINITY;
        float nd1 = (lane + 32 < NP) ? -__ldg(dtj + lane + 32) : -INFINITY;
        float nd2 = (lane + 64 < NP) ? -__ldg(dtj + lane + 64) : -INFINITY;
        float m = fmaxf(nd0, fmaxf(nd1, nd2));
#pragma unroll
        for (int o = 16; o; o >>= 1) m = fmaxf(m, __shfl_xor_sync(0xffffffffu, m, o));
        float s = expf(nd0 - m) + expf(nd1 - m) + expf(nd2 - m);
        s = warp_sum(s);
        if (lane == 0) g_loss[i] = hb + (m + logf(s));
    }

    // ---- last block: deterministic mean ----
    __threadfence();
    __syncthreads();
    if (t == 0) s_last = (atomicAdd(&g_done, 1u) == (unsigned)(gridDim.x - 1));
    __syncthreads();
    if (s_last) {
        __threadfence();
        float s = 0.f;
        for (int k = t; k < NA; k += 256) s += g_loss[k];
        s = warp_sum(s);
        if (lane == 0) rbuf[w] = s;
        __syncthreads();
        if (t == 0) {
            float total = 0.f;
#pragma unroll
            for (int q = 0; q < 8; q++) total += rbuf[q];
            out[0] = total / (float)NA;
            g_done = 0;
        }
    }
}

// ---------------- launch ------------------------------------------------------
extern "C" void kernel_launch(void* const* d_in, const int* in_sizes, int n_in,
                              void* d_out, int out_size) {
    const float* z       = (const float*)d_in[0];
    const int*   y_idx   = (const int*)d_in[1];
    const float* proxies = (const float*)d_in[2];
    const int*   y_map   = (const int*)d_in[3];
    float*       out     = (float*)d_out;

    cudaFuncSetAttribute(k_dist, cudaFuncAttributeMaxDynamicSharedMemorySize,
                         SMEM_DYN_BYTES);
    k_dist<<<129, DTHR, SMEM_DYN_BYTES>>>(z, y_idx, y_map, proxies);
    k_hard<<<HGRID, 256>>>(out);
}

// round 12
// speedup vs baseline: 2.0051x; 1.0115x over previous
#include <cuda_runtime.h>
#include <cuda_bf16.h>
#include <math.h>

#define BN     8192
#define ZD     128
#define NC     62
#define NP     93
#define P2     96        // padded proxies
#define NA     2730      // anchors 0,3,...,8187
#define EPSV   1e-6f
#define EPS2T  1.28e-10f // ZD*EPS^2
#define SZP    132       // padded smem row pitch (floats) for z AND prx
#define SDP    68        // padded dpz-transpose pitch
#define DTHR   512       // 16 warps; warp = 4 samples x 96 proxies
#define AB_BLK 4         // anchors per k_hard block (2 warps each)
#define HGRID  ((NA + AB_BLK - 1) / AB_BLK)   // 683

#define SMEM_Z_FLOATS  (64 * SZP)     // 8448 (overlaid by s_dpz 96*68=6528)
#define SMEM_P_FLOATS  (P2 * SZP)     // 12672
#define SMEM_DYN_BYTES ((SMEM_Z_FLOATS + SMEM_P_FLOATS) * 4)   // 84480

// ---------------- persistent scratch (device globals, zero-init) -------------
__device__ int   g_clsidx[BN];
__device__ int4  g_meta[NA];           // .x = nearest proxy, .y = lo, .z = hi
__device__ float g_Dpz[P2 * BN];       // dist(proxy p, z j), eps sign psum-zs
__device__ float g_DT [BN * P2];       // dist(z j, proxy p), eps sign zs-psum
__device__ float g_loss[NA];
__device__ unsigned int g_done;

// ---------------- helpers ---------------------------------------------------
__device__ __forceinline__ float warp_sum(float v) {
#pragma unroll
    for (int o = 16; o; o >>= 1) v += __shfl_xor_sync(0xffffffffu, v, o);
    return v;
}
__device__ __forceinline__ void warp_argmin(float& v, int& i) {
#pragma unroll
    for (int o = 16; o; o >>= 1) {
        float v2 = __shfl_xor_sync(0xffffffffu, v, o);
        int   i2 = __shfl_xor_sync(0xffffffffu, i, o);
        if (v2 < v || (v2 == v && i2 < i)) { v = v2; i = i2; }
    }
}
__device__ __forceinline__ void warp_argmax(float& v, int& i) {
#pragma unroll
    for (int o = 16; o; o >>= 1) {
        float v2 = __shfl_xor_sync(0xffffffffu, v, o);
        int   i2 = __shfl_xor_sync(0xffffffffu, i, o);
        if (v2 > v || (v2 == v && i2 < i)) { v = v2; i = i2; }
    }
}

// ============ K1: distances + nearest-proxy + class lists ====================
// grid: 129 x 512. Blocks 0..127: 96x64 tiles. Block 128: scatter + meta.
__global__ void __launch_bounds__(DTHR) k_dist(const float* __restrict__ z,
                                               const int* __restrict__ y_idx,
                                               const int* __restrict__ y_map,
                                               const float* __restrict__ proxies) {
    extern __shared__ float smem[];
    float* s_z   = smem;                  // [64][SZP]; reused as s_dpz[96][SDP]
    float* s_prx = smem + SMEM_Z_FLOATS;  // [P2][SZP]  row-major [p][k]
    __shared__ float s_zz[64], s_zs[64];
    __shared__ float s_pss[P2], s_psum[P2];

    int b = blockIdx.x, t = threadIdx.x;
    int w = t >> 5, lane = t & 31;

    if (b == 128) {    // ---- service: y_rel + scatter + per-anchor bounds ----
        __shared__ int s_inv[NC];
        __shared__ int cnt[NC], cur[NC], start[NC + 1];
        if (t < NC) { s_inv[y_map[t]] = t; cnt[t] = 0; }
        __syncthreads();
        for (int j = t; j < BN; j += DTHR) atomicAdd(&cnt[s_inv[y_idx[j]]], 1);
        __syncthreads();
        if (t == 0) {
            int acc = 0;
            for (int c = 0; c < NC; c++) { start[c] = acc; acc += cnt[c]; }
            start[NC] = acc;
        }
        __syncthreads();
        if (t < NC) cur[t] = start[t];
        __syncthreads();
        for (int j = t; j < BN; j += DTHR) {
            int c = s_inv[y_idx[j]];
            int pos = atomicAdd(&cur[c], 1);
            g_clsidx[pos] = j;
        }
        for (int i = t; i < NA; i += DTHR) {
            int c = s_inv[y_idx[3 * i]];
            g_meta[i].y = start[c];
            g_meta[i].z = start[c + 1];
        }
        return;
    }

    // ---- stage 64 z rows (warp-aligned stride -> free per-row stats) ----
    int B0 = b * 64;
    const float4* z4 = (const float4*)z;
    for (int idx = t; idx < 64 * 32; idx += DTHR) {
        int r = idx >> 5, q = idx & 31;          // r warp-uniform
        float4 v = z4[(size_t)(B0 + r) * 32 + q];
        *(float4*)&s_z[r * SZP + 4 * q] = v;
        float s  = (v.x + v.y) + (v.z + v.w);
        float ss = (v.x * v.x + v.y * v.y) + (v.z * v.z + v.w * v.w);
#pragma unroll
        for (int o = 16; o; o >>= 1) {
            s  += __shfl_xor_sync(0xffffffffu, s, o);
            ss += __shfl_xor_sync(0xffffffffu, ss, o);
        }
        if (lane == 0) { s_zs[r] = s; s_zz[r] = ss; }
    }
    // ---- normalize proxies into smem [p][k] (warp per proxy, 16 warps) ----
    for (int p = w; p < NP; p += 16) {
        float4 v = ((const float4*)(proxies + p * ZD))[lane];
        float ss = warp_sum(v.x * v.x + v.y * v.y + v.z * v.z + v.w * v.w);
        float inv = 1.f / fmaxf(sqrtf(ss), 1e-12f);
        float4 o = make_float4(v.x * inv, v.y * inv, v.z * inv, v.w * inv);
        *(float4*)&s_prx[p * SZP + 4 * lane] = o;
        float so  = warp_sum(o.x + o.y + o.z + o.w);
        float so2 = warp_sum(o.x * o.x + o.y * o.y + o.z * o.z + o.w * o.w);
        if (lane == 0) { s_psum[p] = so; s_pss[p] = so2; }
    }
    // zero pad proxy rows 93..95 + pad stats
    for (int idx = t; idx < 3 * 32; idx += DTHR)
        *(float4*)&s_prx[(NP + idx / 32) * SZP + 4 * (idx % 32)] =
            make_float4(0.f, 0.f, 0.f, 0.f);
    if (t >= NP && t < P2) { s_pss[t] = 0.f; s_psum[t] = 0.f; }
    __syncthreads();

    // ---- mainloop: warp = samples [4w,4w+4) x 96 proxies, float4 over k ----
    int sl = 4 * w;
    const float* pr0 = &s_prx[(lane)      * SZP];
    const float* pr1 = &s_prx[(lane + 32) * SZP];
    const float* pr2 = &s_prx[(lane + 64) * SZP];
    const float* zr0 = &s_z[(sl + 0) * SZP];
    const float* zr1 = &s_z[(sl + 1) * SZP];
    const float* zr2 = &s_z[(sl + 2) * SZP];
    const float* zr3 = &s_z[(sl + 3) * SZP];

    float acc[3][4];
#pragma unroll
    for (int q = 0; q < 3; q++)
#pragma unroll
        for (int i = 0; i < 4; i++) acc[q][i] = 0.f;

#pragma unroll 4
    for (int k4 = 0; k4 < 32; k4++) {
        int ko = 4 * k4;
        float4 p0 = *(const float4*)&pr0[ko];   // conflict-free (132-pitch)
        float4 p1 = *(const float4*)&pr1[ko];
        float4 p2 = *(const float4*)&pr2[ko];
        float4 zv0 = *(const float4*)&zr0[ko];  // broadcasts
        float4 zv1 = *(const float4*)&zr1[ko];
        float4 zv2 = *(const float4*)&zr2[ko];
        float4 zv3 = *(const float4*)&zr3[ko];
#define DOT4(q, pv, i, zv) \
        acc[q][i] = fmaf(pv.x, zv.x, acc[q][i]); \
        acc[q][i] = fmaf(pv.y, zv.y, acc[q][i]); \
        acc[q][i] = fmaf(pv.z, zv.z, acc[q][i]); \
        acc[q][i] = fmaf(pv.w, zv.w, acc[q][i]);
        DOT4(0, p0, 0, zv0) DOT4(0, p0, 1, zv1) DOT4(0, p0, 2, zv2) DOT4(0, p0, 3, zv3)
        DOT4(1, p1, 0, zv0) DOT4(1, p1, 1, zv1) DOT4(1, p1, 2, zv2) DOT4(1, p1, 3, zv3)
        DOT4(2, p2, 0, zv0) DOT4(2, p2, 1, zv1) DOT4(2, p2, 2, zv2) DOT4(2, p2, 3, zv3)
#undef DOT4
    }

    // ---- epilogue: distances; DT rows direct; Dpz via smem transpose ----
    float pss0 = s_pss[lane],      psm0 = s_psum[lane];
    float pss1 = s_pss[lane + 32], psm1 = s_psum[lane + 32];
    float pss2 = s_pss[lane + 64], psm2 = s_psum[lane + 64];
    float zzv[4], zsv[4];
#pragma unroll
    for (int i = 0; i < 4; i++) { zzv[i] = s_zz[sl + i]; zsv[i] = s_zs[sl + i]; }

    __syncthreads();                       // all mainloop smem reads done
    float* s_dpz = s_z;                    // overlay: [96][SDP]

#pragma unroll
    for (int i = 0; i < 4; i++) {
        int sglob = B0 + sl + i;
        float base0 = zzv[i] + pss0 - 2.f * acc[0][i];
        float base1 = zzv[i] + pss1 - 2.f * acc[1][i];
        float base2 = zzv[i] + pss2 - 2.f * acc[2][i];
        float e0 = 2.f * EPSV * (psm0 - zsv[i]);
        float e1 = 2.f * EPSV * (psm1 - zsv[i]);
        float e2 = 2.f * EPSV * (psm2 - zsv[i]);
        float dpz0 = sqrtf(fmaxf(base0 + e0 + EPS2T, 0.f));
        float dpz1 = sqrtf(fmaxf(base1 + e1 + EPS2T, 0.f));
        float dpz2 = sqrtf(fmaxf(base2 + e2 + EPS2T, 0.f));
        float dzp0 = sqrtf(fmaxf(base0 - e0 + EPS2T, 0.f));
        float dzp1 = sqrtf(fmaxf(base1 - e1 + EPS2T, 0.f));
        float dzp2 = sqrtf(fmaxf(base2 - e2 + EPS2T, 0.f));

        // DT: coalesced row writes
        float* dt = g_DT + (size_t)sglob * P2;
        dt[lane] = dzp0; dt[lane + 32] = dzp1; dt[lane + 64] = dzp2;

        // dpz into transpose buffer
        int sc = sl + i;
        s_dpz[(lane)      * SDP + sc] = dpz0;
        s_dpz[(lane + 32) * SDP + sc] = dpz1;
        s_dpz[(lane + 64) * SDP + sc] = dpz2;

        // nearest-proxy argmin for anchor rows (dzp in registers)
        if (sglob % 3 == 0 && sglob / 3 < NA) {
            float bv = dzp0; int bp = lane;
            if (lane + 32 < NP && dzp1 < bv) { bv = dzp1; bp = lane + 32; }
            if (lane + 64 < NP && dzp2 < bv) { bv = dzp2; bp = lane + 64; }
            warp_argmin(bv, bp);
            if (lane == 0) g_meta[sglob / 3].x = bp;
        }
    }
    __syncthreads();

    // coalesced Dpz row writes: 96 rows x 64 floats
    for (int idx = t; idx < 96 * 16; idx += DTHR) {
        int p = idx >> 4, q = idx & 15;
        float4 v = make_float4(s_dpz[p * SDP + 4 * q],     s_dpz[p * SDP + 4 * q + 1],
                               s_dpz[p * SDP + 4 * q + 2], s_dpz[p * SDP + 4 * q + 3]);
        *(float4*)(g_Dpz + (size_t)p * BN + B0 + 4 * q) = v;
    }
}

// ============ K2: 2 warps per anchor: hardpos + lse + mean ===================
// grid: HGRID x 256 (8 warps = 4 anchors per block)
__global__ void __launch_bounds__(256) k_hard(float* __restrict__ out) {
    __shared__ float s_hb[AB_BLK][2];
    __shared__ int   s_hj[AB_BLK][2];
    __shared__ float s_m [AB_BLK][2];
    __shared__ float s_s [AB_BLK][2];
    __shared__ float rbuf[8];
    __shared__ int s_last;
    int t = threadIdx.x, w = t >> 5, lane = t & 31;
    int pair = w >> 1, ws = w & 1;
    int i = blockIdx.x * AB_BLK + pair;
    bool active = (i < NA);

    int a = 0, hjc = 0;
    float nd0 = -INFINITY, nd1 = -INFINITY, hbc = -INFINITY;

    if (active) {
        a = 3 * i;
        int4 mm = __ldg(&g_meta[i]);         // px, lo, hi in one LDG.128
        int px = mm.x, lo = mm.y, hi = mm.z;
        const float* Drow = g_Dpz + (size_t)px * BN;

        // warp ws covers strips [lo + 96*ws, +96); tail strided 64
        int base = lo + 96 * ws;
        int jj[3];
#pragma unroll
        for (int q = 0; q < 3; q++) {
            int idx = base + lane + 32 * q;
            jj[q] = (idx < hi) ? __ldg(g_clsidx + idx) : -1;
        }
        float hb = -INFINITY; int hj = 0x7fffffff;
#pragma unroll
        for (int q = 0; q < 3; q++) {
            int j = jj[q];
            if (j >= a) {
                float d = __ldg(Drow + j);
                if (d > hb || (d == hb && j < hj)) { hb = d; hj = j; }
            }
        }
        for (int idx = lo + 192 + lane + 32 * ws; idx < hi; idx += 64) {
            int j = __ldg(g_clsidx + idx);
            if (j >= a) {
                float d = __ldg(Drow + j);
                if (d > hb || (d == hb && j < hj)) { hb = d; hj = j; }
            }
        }
        warp_argmax(hb, hj);
        if (lane == 0) { s_hb[pair][ws] = hb; s_hj[pair][ws] = hj; }
    }
    __syncthreads();

    if (active) {
        hbc = s_hb[pair][0]; hjc = s_hj[pair][0];
        float hb1 = s_hb[pair][1]; int hj1 = s_hj[pair][1];
        if (hb1 > hbc || (hb1 == hbc && hj1 < hjc)) { hbc = hb1; hjc = hj1; }

        // split logsumexp over 93 proxies: ws0 -> p in [0,32)+[64,93); ws1 -> [32,64)
        const float* dtj = g_DT + (size_t)hjc * P2;
        if (ws == 0) {
            nd0 = -__ldg(dtj + lane);
            nd1 = (lane + 64 < NP) ? -__ldg(dtj + lane + 64) : -INFINITY;
        } else {
            nd0 = -__ldg(dtj + lane + 32);
        }
        float m = fmaxf(nd0, nd1);
#pragma unroll
        for (int o = 16; o; o >>= 1) m = fmaxf(m, __shfl_xor_sync(0xffffffffu, m, o));
        if (lane == 0) s_m[pair][ws] = m;
    }
    __syncthreads();

    if (active) {
        float m = fmaxf(s_m[pair][0], s_m[pair][1]);
        float e = expf(nd0 - m) + expf(nd1 - m);
        float s = warp_sum(e);
        if (lane == 0) s_s[pair][ws] = s;
        // stash m for the writer via register (recomputed identically by ws0)
        if (ws == 0 && lane == 0) s_m[pair][0] = m;   // overwrite with combined
    }
    __syncthreads();

    if (active && ws == 0 && lane == 0) {
        float s = s_s[pair][0] + s_s[pair][1];
        g_loss[i] = hbc + (s_m[pair][0] + logf(s));
    }

    // ---- last block: deterministic mean ----
    __threadfence();
    __syncthreads();
    if (t == 0) s_last = (atomicAdd(&g_done, 1u) == (unsigned)(gridDim.x - 1));
    __syncthreads();
    if (s_last) {
        __threadfence();
        float s = 0.f;
        for (int k = t; k < NA; k += 256) s += g_loss[k];
        s = warp_sum(s);
        if (lane == 0) rbuf[w] = s;
        __syncthreads();
        if (t == 0) {
            float total = 0.f;
#pragma unroll
            for (int q = 0; q < 8; q++) total += rbuf[q];
            out[0] = total / (float)NA;
            g_done = 0;
        }
    }
}

// ---------------- launch ------------------------------------------------------
extern "C" void kernel_launch(void* const* d_in, const int* in_sizes, int n_in,
                              void* d_out, int out_size) {
    const float* z       = (const float*)d_in[0];
    const int*   y_idx   = (const int*)d_in[1];
    const float* proxies = (const float*)d_in[2];
    const int*   y_map   = (const int*)d_in[3];
    float*       out     = (float*)d_out;

    cudaFuncSetAttribute(k_dist, cudaFuncAttributeMaxDynamicSharedMemorySize,
                         SMEM_DYN_BYTES);
    k_dist<<<129, DTHR, SMEM_DYN_BYTES>>>(z, y_idx, y_map, proxies);
    k_hard<<<HGRID, 256>>>(out);
}